// round 9
// baseline (speedup 1.0000x reference)
#include <cuda_runtime.h>
#include <cstdint>
#include <math.h>
#include <float.h>

#define NB 4096
#define TT 200
#define DD 64
#define H1 16
#define H2 8
#define TILE_FLOATS (TT * DD)            // 12800
#define TILE_BYTES  (TILE_FLOATS * 4)    // 51200
#define HPITCH 20                        // hbuf pitch in floats (80B rows)

#define NEG_INF_F (-4294967296.0f)       // fp32 rounding of -(2^32)+1

typedef unsigned long long ull;

__device__ __forceinline__ void cp_async16(uint32_t smem_dst, const void* gsrc) {
    asm volatile("cp.async.cg.shared.global [%0], [%1], 16;\n"
                 :: "r"(smem_dst), "l"(gsrc));
}
__device__ __forceinline__ void cp_async_wait_all() {
    asm volatile("cp.async.wait_all;\n" ::: "memory");
}
__device__ __forceinline__ float fsigmoid(float x) {
    return __fdividef(1.0f, 1.0f + __expf(-x));
}
// ---- packed f32x2 helpers ----
__device__ __forceinline__ ull pack2(float x, float y) {
    ull r; asm("mov.b64 %0, {%1, %2};" : "=l"(r) : "f"(x), "f"(y)); return r;
}
__device__ __forceinline__ void unpack2(ull v, float& x, float& y) {
    asm("mov.b64 {%0, %1}, %2;" : "=f"(x), "=f"(y) : "l"(v));
}
__device__ __forceinline__ ull fma2(ull a, ull b, ull c) {
    ull d; asm("fma.rn.f32x2 %0, %1, %2, %3;" : "=l"(d) : "l"(a), "l"(b), "l"(c));
    return d;
}
__device__ __forceinline__ void lds_v2u64(uint32_t saddr, ull& a, ull& b) {
    asm volatile("ld.shared.v2.u64 {%0, %1}, [%2];"
                 : "=l"(a), "=l"(b) : "r"(saddr));
}

__global__ __launch_bounds__(256, 3)
void din_attn_kernel(const float* __restrict__ qg,
                     const float* __restrict__ kg,
                     const int*   __restrict__ lg,
                     const float* __restrict__ W1,
                     const float* __restrict__ b1,
                     const float* __restrict__ W2,
                     const float* __restrict__ b2,
                     const float* __restrict__ W3,
                     const float* __restrict__ b3,
                     const float* __restrict__ W4,
                     const float* __restrict__ b4,
                     float* __restrict__ outg)
{
    extern __shared__ float k_s[];                  // dense swizzled tile, 51200 B
    __shared__ __align__(16) float M_s[DD * H1];    // effective W1 (64x16), 4 KB
    __shared__ __align__(16) float hbuf[TT * HPITCH]; // 16 KB: h1 exchange / scratch
    __shared__ float q_s[DD];
    __shared__ float v_s[H1];
    __shared__ float W2_s[H1 * H2];
    __shared__ float b2_s[H2];
    __shared__ float W3_s[H2];
    __shared__ float red_s[8];
    __shared__ float b3_s;

    const int b   = blockIdx.x;
    const int tid = threadIdx.x;
    const uint32_t sb = (uint32_t)__cvta_generic_to_shared(k_s);
    const uint32_t Mb = (uint32_t)__cvta_generic_to_shared(M_s);

    // ---- issue ALL key-tile copies asynchronously (XOR-quad swizzle) ----
    {
        const char* g = (const char*)(kg + (size_t)b * TILE_FLOATS);
        #pragma unroll
        for (int it = 0; it < 12; it++) {
            int i = tid + it * 256;
            int t = i >> 4, c = i & 15;
            cp_async16(sb + t * 256 + ((c ^ (t & 15)) << 4), g + i * 16);
        }
        if (tid < 128) {
            int i = tid + 3072;
            int t = i >> 4, c = i & 15;
            cp_async16(sb + t * 256 + ((c ^ (t & 15)) << 4), g + i * 16);
        }
    }

    // ---- tiny parameter loads (overlap with async copies) ----
    if (tid < DD)      q_s[tid]  = qg[(size_t)b * DD + tid];
    if (tid >= 64 && tid < 64 + H1 * H2) W2_s[tid - 64] = W2[tid - 64];
    if (tid >= 192 && tid < 192 + H2)    { b2_s[tid - 192] = b2[tid - 192]; W3_s[tid - 192] = W3[tid - 192]; }
    if (tid == 255)    b3_s = b3[0];
    __syncthreads();

    // ---- M[d][h] = W1b - W1c + q_d * W1d ----
    for (int i = tid; i < DD * H1; i += 256) {
        int d = i >> 4, h = i & 15;
        M_s[i] = W1[(64 + d) * H1 + h] - W1[(128 + d) * H1 + h]
               + q_s[d] * W1[(192 + d) * H1 + h];
    }
    // ---- v[h] = b1 + q @ (W1a + W1c) ----
    if (tid < H1) {
        float a0 = 0.f, a1 = 0.f;
        #pragma unroll 8
        for (int d = 0; d < DD; d += 2) {
            a0 = fmaf(q_s[d + 0], W1[(d + 0) * H1 + tid] + W1[(128 + d + 0) * H1 + tid], a0);
            a1 = fmaf(q_s[d + 1], W1[(d + 1) * H1 + tid] + W1[(128 + d + 1) * H1 + tid], a1);
        }
        v_s[tid] = b1[tid] + a0 + a1;
    }

    const int len = lg[b];

    cp_async_wait_all();
    __syncthreads();

    const float4* k4 = reinterpret_cast<const float4*>(k_s);

    // ---- pass 1a: 4t x 4h register-tiled scorer GEMM ----
    // thread (tg, hg): t in {tg, tg+50, tg+100, tg+150}, h in [4hg, 4hg+4)
    if (tid < 200) {
        const int tg = tid >> 2, hg = tid & 3;
        int trow[4], tx[4];
        #pragma unroll
        for (int jt = 0; jt < 4; jt++) {
            int t = tg + 50 * jt;
            trow[jt] = t * 16;
            tx[jt]   = t & 15;
        }
        ull acc[4][2];
        {
            ull b0 = pack2(v_s[hg * 4 + 0], v_s[hg * 4 + 1]);
            ull b1p = pack2(v_s[hg * 4 + 2], v_s[hg * 4 + 3]);
            #pragma unroll
            for (int jt = 0; jt < 4; jt++) { acc[jt][0] = b0; acc[jt][1] = b1p; }
        }

        #pragma unroll 8
        for (int db = 0; db < 16; db++) {
            float4 kv[4];
            #pragma unroll
            for (int jt = 0; jt < 4; jt++)
                kv[jt] = k4[trow[jt] + (db ^ tx[jt])];
            ull m[4][2];
            #pragma unroll
            for (int jd = 0; jd < 4; jd++)
                lds_v2u64(Mb + (db * 4 + jd) * 64 + hg * 16, m[jd][0], m[jd][1]);
            #pragma unroll
            for (int jt = 0; jt < 4; jt++) {
                #pragma unroll
                for (int jd = 0; jd < 4; jd++) {
                    float kd = (jd == 0) ? kv[jt].x : (jd == 1) ? kv[jt].y
                             : (jd == 2) ? kv[jt].z : kv[jt].w;
                    ull kp = pack2(kd, kd);
                    acc[jt][0] = fma2(kp, m[jd][0], acc[jt][0]);
                    acc[jt][1] = fma2(kp, m[jd][1], acc[jt][1]);
                }
            }
        }

        // sigmoid + hand off h1 quads to hbuf (pitch 20 floats)
        #pragma unroll
        for (int jt = 0; jt < 4; jt++) {
            float f0, f1, f2, f3;
            unpack2(acc[jt][0], f0, f1);
            unpack2(acc[jt][1], f2, f3);
            float4 o;
            o.x = fsigmoid(f0); o.y = fsigmoid(f1);
            o.z = fsigmoid(f2); o.w = fsigmoid(f3);
            *reinterpret_cast<float4*>(hbuf + (tg + 50 * jt) * HPITCH + hg * 4) = o;
        }
    }
    __syncthreads();

    // ---- pass 1b: tail MLP, one t per thread ----
    float s = -FLT_MAX;
    if (tid < TT) {
        float h[H1];
        const float4* hb = reinterpret_cast<const float4*>(hbuf + tid * HPITCH);
        #pragma unroll
        for (int sq = 0; sq < 4; sq++) {
            float4 v = hb[sq];
            h[sq * 4 + 0] = v.x; h[sq * 4 + 1] = v.y;
            h[sq * 4 + 2] = v.z; h[sq * 4 + 3] = v.w;
        }
        float x2[H2];
        #pragma unroll
        for (int k = 0; k < H2; k++) {
            float a = b2_s[k];
            #pragma unroll
            for (int j = 0; j < H1; j++) a = fmaf(h[j], W2_s[j * H2 + k], a);
            x2[k] = fsigmoid(a);
        }
        float sc = b3_s;
        #pragma unroll
        for (int k = 0; k < H2; k++) sc = fmaf(x2[k], W3_s[k], sc);

        sc = (tid < len) ? sc : NEG_INF_F;
        s = sc * 0.125f;   // 1/sqrt(64) after masking, as in reference
    }

    // ---- block softmax max (len==0 must give uniform attention) ----
    float val = s;
    #pragma unroll
    for (int o = 16; o; o >>= 1) val = fmaxf(val, __shfl_xor_sync(0xffffffffu, val, o));
    if ((tid & 31) == 0) red_s[tid >> 5] = val;
    __syncthreads();
    float mx = red_s[0];
    #pragma unroll
    for (int i = 1; i < 8; i++) mx = fmaxf(mx, red_s[i]);
    __syncthreads();   // all hbuf reads done; hbuf reusable as scratch

    float* sc_s = hbuf;           // [200]
    float* op_s = hbuf + 256;     // [8][64]
    float* o_s  = hbuf + 768;     // [64]

    // ---- exp + sum ----
    float p = 0.0f;
    if (tid < TT) { p = __expf(s - mx); sc_s[tid] = p; }
    #pragma unroll
    for (int o = 16; o; o >>= 1) p += __shfl_xor_sync(0xffffffffu, p, o);
    if ((tid & 31) == 0) red_s[tid >> 5] = p;
    __syncthreads();
    float denom = 0.0f;
    #pragma unroll
    for (int i = 0; i < 8; i++) denom += red_s[i];
    float inv = __fdividef(1.0f, denom);

    // ---- pass 2: weighted key sum, 128 threads = 8 t-groups x 16 d-quads ----
    if (tid < 128) {
        int g = tid >> 4, dq = tid & 15;
        int tb = g * 25;
        float4 acc = make_float4(0.f, 0.f, 0.f, 0.f);
        #pragma unroll 5
        for (int i = 0; i < 25; i++) {
            int t = tb + i;
            float w = sc_s[t];
            float4 kv = k4[t * 16 + (dq ^ (t & 15))];
            acc.x = fmaf(w, kv.x, acc.x);
            acc.y = fmaf(w, kv.y, acc.y);
            acc.z = fmaf(w, kv.z, acc.z);
            acc.w = fmaf(w, kv.w, acc.w);
        }
        *reinterpret_cast<float4*>(op_s + g * 64 + dq * 4) = acc;
    }
    __syncthreads();
    if (tid < DD) {
        float sum = 0.f;
        #pragma unroll
        for (int g = 0; g < 8; g++) sum += op_s[g * 64 + tid];
        o_s[tid] = sum * inv;
    }
    __syncthreads();

    // ---- projection partials: thread (g,d) sums dp in [g*16, g*16+16) ----
    {
        int g = tid >> 6, d = tid & 63;
        int dp0 = g * 16;
        float a0 = 0.f, a1 = 0.f;
        #pragma unroll
        for (int dp = 0; dp < 16; dp += 2) {
            a0 = fmaf(o_s[dp0 + dp],     W4[(dp0 + dp)     * DD + d], a0);
            a1 = fmaf(o_s[dp0 + dp + 1], W4[(dp0 + dp + 1) * DD + d], a1);
        }
        op_s[g * 64 + d] = a0 + a1;
    }
    __syncthreads();
    if (tid < DD)
        outg[(size_t)b * DD + tid] =
            (op_s[tid] + op_s[64 + tid]) + (op_s[128 + tid] + op_s[192 + tid]) + b4[tid];
}

extern "C" void kernel_launch(void* const* d_in, const int* in_sizes, int n_in,
                              void* d_out, int out_size)
{
    const float* q  = (const float*)d_in[0];
    const float* k  = (const float*)d_in[1];
    const int*   l  = (const int*)d_in[2];
    const float* W1 = (const float*)d_in[3];
    const float* b1 = (const float*)d_in[4];
    const float* W2 = (const float*)d_in[5];
    const float* b2 = (const float*)d_in[6];
    const float* W3 = (const float*)d_in[7];
    const float* b3 = (const float*)d_in[8];
    const float* W4 = (const float*)d_in[9];
    const float* b4 = (const float*)d_in[10];
    float* out = (float*)d_out;

    const int smem_bytes = TILE_BYTES;   // 51200 B dynamic
    cudaFuncSetAttribute(din_attn_kernel,
                         cudaFuncAttributeMaxDynamicSharedMemorySize, smem_bytes);

    din_attn_kernel<<<NB, 256, smem_bytes>>>(q, k, l, W1, b1, W2, b2,
                                             W3, b3, W4, b4, out);
}

// round 11
// speedup vs baseline: 1.4065x; 1.4065x over previous
#include <cuda_runtime.h>
#include <cstdint>
#include <math.h>
#include <float.h>

#define NB 4096
#define TT 200
#define DD 64
#define H1 16
#define H2 8
#define TILE_FLOATS (TT * DD)            // 12800
#define TILE_BYTES  (TILE_FLOATS * 4)    // 51200

#define NEG_INF_F (-4294967296.0f)       // fp32 rounding of -(2^32)+1

typedef unsigned long long ull;

__device__ __forceinline__ void cp_async16(uint32_t smem_dst, const void* gsrc) {
    asm volatile("cp.async.cg.shared.global [%0], [%1], 16;\n"
                 :: "r"(smem_dst), "l"(gsrc));
}
__device__ __forceinline__ void cp_async_wait_all() {
    asm volatile("cp.async.wait_all;\n" ::: "memory");
}
__device__ __forceinline__ float fsigmoid(float x) {
    return __fdividef(1.0f, 1.0f + __expf(-x));
}
// ---- packed f32x2 helpers ----
__device__ __forceinline__ ull pack2(float x, float y) {
    ull r; asm("mov.b64 %0, {%1, %2};" : "=l"(r) : "f"(x), "f"(y)); return r;
}
__device__ __forceinline__ void unpack2(ull v, float& x, float& y) {
    asm("mov.b64 {%0, %1}, %2;" : "=f"(x), "=f"(y) : "l"(v));
}
__device__ __forceinline__ ull fma2(ull a, ull b, ull c) {
    ull d; asm("fma.rn.f32x2 %0, %1, %2, %3;" : "=l"(d) : "l"(a), "l"(b), "l"(c));
    return d;
}
__device__ __forceinline__ void lds_v2u64(uint32_t saddr, ull& a, ull& b) {
    asm volatile("ld.shared.v2.u64 {%0, %1}, [%2];"
                 : "=l"(a), "=l"(b) : "r"(saddr));
}

__global__ __launch_bounds__(128, 4)
void din_attn_kernel(const float* __restrict__ qg,
                     const float* __restrict__ kg,
                     const int*   __restrict__ lg,
                     const float* __restrict__ W1,
                     const float* __restrict__ b1,
                     const float* __restrict__ W2,
                     const float* __restrict__ b2,
                     const float* __restrict__ W3,
                     const float* __restrict__ b3,
                     const float* __restrict__ W4,
                     const float* __restrict__ b4,
                     float* __restrict__ outg)
{
    extern __shared__ float k_s[];                  // dense swizzled tile, 51200 B
    __shared__ __align__(16) float U[1024];         // M (pass1) -> sc/op/o (later)
    __shared__ float v_s[H1];
    __shared__ float W2_s[H1 * H2];
    __shared__ float b2_s[H2];
    __shared__ float W3_s[H2];
    __shared__ float red_s[4];
    __shared__ float b3_s;

    const int b   = blockIdx.x;
    const int tid = threadIdx.x;
    const uint32_t sb = (uint32_t)__cvta_generic_to_shared(k_s);
    const uint32_t Mb = (uint32_t)__cvta_generic_to_shared(U);

    // ---- issue ALL key-tile copies asynchronously (XOR-quad swizzle) ----
    {
        const char* g = (const char*)(kg + (size_t)b * TILE_FLOATS);
        #pragma unroll
        for (int it = 0; it < 25; it++) {           // 25*128 = 3200 float4s exactly
            int i = tid + it * 128;
            int t = i >> 4, c = i & 15;
            cp_async16(sb + t * 256 + ((c ^ (t & 15)) << 4), g + i * 16);
        }
    }

    // ---- tiny parameter loads (overlap with async copies) ----
    W2_s[tid] = W2[tid];                            // 128 elements, 128 threads
    if (tid < H2) { b2_s[tid] = b2[tid]; W3_s[tid] = W3[tid]; }
    if (tid == 127) b3_s = b3[0];

    // ---- M[d][h] = W1b - W1c + q_d * W1d  (into U; q via L1-cached LDG) ----
    const float* qrow = qg + (size_t)b * DD;
    #pragma unroll
    for (int it = 0; it < 8; it++) {                // 8*128 = 1024
        int i = tid + it * 128;
        int d = i >> 4, h = i & 15;
        U[i] = W1[(64 + d) * H1 + h] - W1[(128 + d) * H1 + h]
             + qrow[d] * W1[(192 + d) * H1 + h];
    }
    // ---- v[h] = b1 + q @ (W1a + W1c) ----
    if (tid < H1) {
        float a0 = 0.f, a1 = 0.f;
        #pragma unroll 8
        for (int d = 0; d < DD; d += 2) {
            a0 = fmaf(qrow[d + 0], W1[(d + 0) * H1 + tid] + W1[(128 + d + 0) * H1 + tid], a0);
            a1 = fmaf(qrow[d + 1], W1[(d + 1) * H1 + tid] + W1[(128 + d + 1) * H1 + tid], a1);
        }
        v_s[tid] = b1[tid] + a0 + a1;
    }

    const int len = lg[b];

    cp_async_wait_all();
    __syncthreads();

    const float4* k4 = reinterpret_cast<const float4*>(k_s);

    // ---- pass 1: MLP scorer, thread i<100 handles t0=i, t1=i+100 (R4 core) ----
    float s0 = -FLT_MAX, s1 = -FLT_MAX;
    if (tid < 100) {
        const int t0 = tid, t1 = tid + 100;
        const int x0 = t0 & 15, x1 = t1 & 15;
        ull acc0[8], acc1[8];
        #pragma unroll
        for (int j = 0; j < 8; j++) {
            ull v = pack2(v_s[2 * j], v_s[2 * j + 1]);
            acc0[j] = v; acc1[j] = v;
        }

        #pragma unroll 4
        for (int db = 0; db < 16; db++) {
            float4 ka = k4[t0 * 16 + (db ^ x0)];
            float4 kb = k4[t1 * 16 + (db ^ x1)];
            #pragma unroll
            for (int sub = 0; sub < 4; sub++) {
                float a = (sub == 0) ? ka.x : (sub == 1) ? ka.y : (sub == 2) ? ka.z : ka.w;
                float c = (sub == 0) ? kb.x : (sub == 1) ? kb.y : (sub == 2) ? kb.z : kb.w;
                ull kpa = pack2(a, a);
                ull kpb = pack2(c, c);
                uint32_t off = Mb + (db * 4 + sub) * 64;
                ull m[8];
                lds_v2u64(off +  0, m[0], m[1]);
                lds_v2u64(off + 16, m[2], m[3]);
                lds_v2u64(off + 32, m[4], m[5]);
                lds_v2u64(off + 48, m[6], m[7]);
                #pragma unroll
                for (int j = 0; j < 8; j++) acc0[j] = fma2(kpa, m[j], acc0[j]);
                #pragma unroll
                for (int j = 0; j < 8; j++) acc1[j] = fma2(kpb, m[j], acc1[j]);
            }
        }

        #pragma unroll
        for (int which = 0; which < 2; which++) {
            float h[H1];
            #pragma unroll
            for (int j = 0; j < 8; j++)
                unpack2(which ? acc1[j] : acc0[j], h[2 * j], h[2 * j + 1]);
            #pragma unroll
            for (int j = 0; j < H1; j++) h[j] = fsigmoid(h[j]);

            float x2[H2];
            #pragma unroll
            for (int k = 0; k < H2; k++) {
                float acc = b2_s[k];
                #pragma unroll
                for (int j = 0; j < H1; j++) acc = fmaf(h[j], W2_s[j * H2 + k], acc);
                x2[k] = fsigmoid(acc);
            }
            float sc = b3_s;
            #pragma unroll
            for (int k = 0; k < H2; k++) sc = fmaf(x2[k], W3_s[k], sc);

            if (which == 0) { sc = (t0 < len) ? sc : NEG_INF_F; s0 = sc * 0.125f; }
            else            { sc = (t1 < len) ? sc : NEG_INF_F; s1 = sc * 0.125f; }
        }
    }

    // ---- block softmax max (4 warps; len==0 must give uniform attention) ----
    float val = fmaxf(s0, s1);
    #pragma unroll
    for (int o = 16; o; o >>= 1) val = fmaxf(val, __shfl_xor_sync(0xffffffffu, val, o));
    if ((tid & 31) == 0) red_s[tid >> 5] = val;
    __syncthreads();
    float mx = fmaxf(fmaxf(red_s[0], red_s[1]), fmaxf(red_s[2], red_s[3]));
    __syncthreads();   // M reads done; U reusable as scratch

    float* sc_s = U;           // [200]
    float* op_s = U + 256;     // [8][64]
    float* o_s  = U + 768;     // [64]

    // ---- exp + sum ----
    float p = 0.0f;
    if (tid < 100) {
        float p0 = __expf(s0 - mx);
        float p1 = __expf(s1 - mx);
        sc_s[tid]       = p0;
        sc_s[tid + 100] = p1;
        p = p0 + p1;
    }
    #pragma unroll
    for (int o = 16; o; o >>= 1) p += __shfl_xor_sync(0xffffffffu, p, o);
    if ((tid & 31) == 0) red_s[tid >> 5] = p;
    __syncthreads();
    float denom = (red_s[0] + red_s[1]) + (red_s[2] + red_s[3]);
    float inv = __fdividef(1.0f, denom);

    // ---- pass 2: weighted key sum, 128 threads = 8 t-groups x 16 d-quads ----
    {
        int g = tid >> 4, dq = tid & 15;
        int tb = g * 25;
        float4 acc = make_float4(0.f, 0.f, 0.f, 0.f);
        #pragma unroll 5
        for (int i = 0; i < 25; i++) {
            int t = tb + i;
            float w = sc_s[t];
            float4 kv = k4[t * 16 + (dq ^ (t & 15))];
            acc.x = fmaf(w, kv.x, acc.x);
            acc.y = fmaf(w, kv.y, acc.y);
            acc.z = fmaf(w, kv.z, acc.z);
            acc.w = fmaf(w, kv.w, acc.w);
        }
        *reinterpret_cast<float4*>(op_s + g * 64 + dq * 4) = acc;
    }
    __syncthreads();
    if (tid < DD) {
        float sum = 0.f;
        #pragma unroll
        for (int g = 0; g < 8; g++) sum += op_s[g * 64 + tid];
        o_s[tid] = sum * inv;
    }
    __syncthreads();

    // ---- projection partials: thread (g,d), g in {0,1}, sums 32 dp each ----
    {
        int g = tid >> 6, d = tid & 63;
        int dp0 = g * 32;
        float a0 = 0.f, a1 = 0.f;
        #pragma unroll 8
        for (int dp = 0; dp < 32; dp += 2) {
            a0 = fmaf(o_s[dp0 + dp],     W4[(dp0 + dp)     * DD + d], a0);
            a1 = fmaf(o_s[dp0 + dp + 1], W4[(dp0 + dp + 1) * DD + d], a1);
        }
        op_s[g * 64 + d] = a0 + a1;
    }
    __syncthreads();
    if (tid < DD)
        outg[(size_t)b * DD + tid] = op_s[tid] + op_s[64 + tid] + b4[tid];
}

extern "C" void kernel_launch(void* const* d_in, const int* in_sizes, int n_in,
                              void* d_out, int out_size)
{
    const float* q  = (const float*)d_in[0];
    const float* k  = (const float*)d_in[1];
    const int*   l  = (const int*)d_in[2];
    const float* W1 = (const float*)d_in[3];
    const float* b1 = (const float*)d_in[4];
    const float* W2 = (const float*)d_in[5];
    const float* b2 = (const float*)d_in[6];
    const float* W3 = (const float*)d_in[7];
    const float* b3 = (const float*)d_in[8];
    const float* W4 = (const float*)d_in[9];
    const float* b4 = (const float*)d_in[10];
    float* out = (float*)d_out;

    const int smem_bytes = TILE_BYTES;   // 51200 B dynamic
    cudaFuncSetAttribute(din_attn_kernel,
                         cudaFuncAttributeMaxDynamicSharedMemorySize, smem_bytes);

    din_attn_kernel<<<NB, 128, smem_bytes>>>(q, k, l, W1, b1, W2, b2,
                                             W3, b3, W4, b4, out);
}